// round 12
// baseline (speedup 1.0000x reference)
#include <cuda_runtime.h>
#include <cuda_fp16.h>
#include <cstdint>
#include <math.h>

#define D 128
#define NMAX 100000
#define TMAX 4
#define KAGG ((TMAX + 1) * D)    // 640
#define BK 48                    // per-(type,node) neighbor bucket capacity
#define ASTH 40                  // A chunk row stride (halfs): conflict-free frag loads
#define BSTH 40                  // B chunk row stride (halfs)
#define A_HALFS (128 * ASTH)     // 5120
#define B_HALFS (128 * BSTH)     // 5120
#define STG_HALFS (A_HALFS + B_HALFS)      // 10240
#define SMEM_BYTES (2 * STG_HALFS * 2)     // 40960

// ---------------- device scratch ----------------
__device__ __half g_featH[(size_t)NMAX * D];            // feat fp16 [n][d]
__device__ __half g_WCH[(size_t)TMAX * D * D];          // W_content fp16 [t][o][d]
__device__ __half g_WaggH[(size_t)D * KAGG];            // W_agg^T fp16 [o][k]
__device__ __half g_Hh[(size_t)TMAX * NMAX * D];        // H fp16 [t][n][o]
__device__ int    g_CSR[(size_t)TMAX * NMAX * BK];      // neighbor buckets
__device__ int    g_CUR[TMAX * NMAX];                   // bucket cursors / degrees
__device__ float  g_SUM[D];

// ---------------- helpers ----------------
__device__ __forceinline__ uint32_t smem_u32(const void* p) {
    uint32_t a;
    asm("{ .reg .u64 t; cvta.to.shared.u64 t, %1; cvt.u32.u64 %0, t; }" : "=r"(a) : "l"(p));
    return a;
}
__device__ __forceinline__ void cpa16(uint32_t dst, const void* src, int valid) {
    asm volatile("cp.async.ca.shared.global [%0], [%1], 16, %2;"
                 :: "r"(dst), "l"(src), "r"(valid ? 16 : 0));
}
__device__ __forceinline__ void cpa_commit() { asm volatile("cp.async.commit_group;" ::: "memory"); }
template <int NN> __device__ __forceinline__ void cpa_wait() {
    asm volatile("cp.async.wait_group %0;" :: "n"(NN) : "memory");
}
__device__ __forceinline__ void mma16(float* c, const uint32_t* a, const uint32_t* b) {
    asm volatile("mma.sync.aligned.m16n8k16.row.col.f32.f16.f16.f32 "
                 "{%0,%1,%2,%3},{%4,%5,%6,%7},{%8,%9},{%0,%1,%2,%3};"
                 : "+f"(c[0]), "+f"(c[1]), "+f"(c[2]), "+f"(c[3])
                 : "r"(a[0]), "r"(a[1]), "r"(a[2]), "r"(a[3]), "r"(b[0]), "r"(b[1]));
}
__device__ __forceinline__ uint32_t ldh2(const __half* p) { return *(const uint32_t*)p; }

// ---------------- zero cursors + sums ----------------
__global__ void zero_kernel() {
    int i = blockIdx.x * blockDim.x + threadIdx.x;
    int stride = gridDim.x * blockDim.x;
    for (int k = i; k < TMAX * NMAX; k += stride) g_CUR[k] = 0;
    if (i < D) g_SUM[i] = 0.f;
}

// ---------------- fp32 -> fp16 converts ----------------
__global__ void convert_feat(const float* __restrict__ f, int n2) {
    int i = blockIdx.x * blockDim.x + threadIdx.x;
    if (i < n2) {
        float2 v = ((const float2*)f)[i];
        ((half2*)g_featH)[i] = __floats2half2_rn(v.x, v.y);
    }
}
__global__ void convert_WC(const float* __restrict__ W, int n2) {
    int i = blockIdx.x * blockDim.x + threadIdx.x;
    if (i < n2) {
        float2 v = ((const float2*)W)[i];
        ((half2*)g_WCH)[i] = __floats2half2_rn(v.x, v.y);
    }
}
// W_agg [k=640][o=128] -> g_WaggH [o][k] fp16
__global__ void transpose_Wagg(const float* __restrict__ W) {
    __shared__ float t[32][33];
    int k0 = blockIdx.x * 32, o0 = blockIdx.y * 32;
    int tx = threadIdx.x, ty = threadIdx.y;
#pragma unroll
    for (int i = 0; i < 4; i++)
        t[ty + i * 8][tx] = W[(size_t)(k0 + ty + i * 8) * D + o0 + tx];
    __syncthreads();
#pragma unroll
    for (int i = 0; i < 4; i++)
        g_WaggH[(size_t)(o0 + ty + i * 8) * KAGG + k0 + tx] = __float2half(t[tx][ty + i * 8]);
}

// ---------------- scatter edges into buckets (int atomics only) ----------------
__global__ void scatter_kernel(const int* __restrict__ src, const int* __restrict__ dst,
                               int E, int N, int TE) {
    int g = blockIdx.x * blockDim.x + threadIdx.x;
    if (g >= TE) return;
    int t = g / E;
    int d = __ldg(dst + g);
    int s = __ldg(src + g);
    int tn = t * N + d;
    int pos = atomicAdd(&g_CUR[tn], 1);
    if (pos < BK) g_CSR[(size_t)tn * BK + pos] = s;
}

// ================= content GEMM: fp16 mma, cp.async double-buffered =================
__global__ __launch_bounds__(256, 2) void gemm_content_mma(const float* __restrict__ bc, int N) {
    extern __shared__ __half smh[];
    __shared__ float sBias[128];
    uint32_t smBase = smem_u32(smh);

    int t = blockIdx.y;
    int n0 = blockIdx.x * 128;
    int tid = threadIdx.x, wid = tid >> 5, lane = tid & 31;
    if (tid < 128) sBias[tid] = bc[t * D + tid];

    const __half* wc = g_WCH + (size_t)t * D * D;

    auto load_chunk = [&](int kc, int s) {
        uint32_t aBase = smBase + (uint32_t)s * STG_HALFS * 2;
        uint32_t bBase = aBase + A_HALFS * 2;
#pragma unroll
        for (int i = 0; i < 2; i++) {
            int idx = tid + i * 256;
            int row = idx >> 2, c = idx & 3;
            int n = n0 + row;
            cpa16(aBase + (uint32_t)(row * ASTH + c * 8) * 2,
                  g_featH + (size_t)n * D + kc * 32 + c * 8, n < N);
            cpa16(bBase + (uint32_t)(row * BSTH + c * 8) * 2,
                  wc + (size_t)row * D + kc * 32 + c * 8, 1);
        }
        cpa_commit();
    };

    int m0 = (wid & 3) * 32, nw = (wid >> 2) * 64;
    int g = lane >> 2, tg = lane & 3;

    float c[2][8][4];
#pragma unroll
    for (int mt = 0; mt < 2; mt++)
#pragma unroll
        for (int nt = 0; nt < 8; nt++)
#pragma unroll
            for (int j = 0; j < 4; j++) c[mt][nt][j] = 0.f;

    load_chunk(0, 0);
    for (int cc = 0; cc < 4; cc++) {
        if (cc + 1 < 4) { load_chunk(cc + 1, (cc + 1) & 1); cpa_wait<1>(); }
        else            { cpa_wait<0>(); }
        __syncthreads();
        const __half* As = smh + (cc & 1) * STG_HALFS;
        const __half* Bs = As + A_HALFS;
#pragma unroll
        for (int s16 = 0; s16 < 2; s16++) {
            uint32_t a[2][4], b[8][2];
#pragma unroll
            for (int mt = 0; mt < 2; mt++) {
                const __half* ap = As + (m0 + mt * 16 + g) * ASTH + s16 * 16 + 2 * tg;
                a[mt][0] = ldh2(ap);
                a[mt][1] = ldh2(ap + 8 * ASTH);
                a[mt][2] = ldh2(ap + 8);
                a[mt][3] = ldh2(ap + 8 * ASTH + 8);
            }
#pragma unroll
            for (int nt = 0; nt < 8; nt++) {
                const __half* bp = Bs + (nw + nt * 8 + g) * BSTH + s16 * 16 + 2 * tg;
                b[nt][0] = ldh2(bp);
                b[nt][1] = ldh2(bp + 8);
            }
#pragma unroll
            for (int mt = 0; mt < 2; mt++)
#pragma unroll
                for (int nt = 0; nt < 8; nt++) mma16(c[mt][nt], a[mt], b[nt]);
        }
        __syncthreads();
    }

#pragma unroll
    for (int mt = 0; mt < 2; mt++) {
#pragma unroll
        for (int nt = 0; nt < 8; nt++) {
            int col = nw + nt * 8 + 2 * tg;
            float b0 = sBias[col], b1 = sBias[col + 1];
            int n = n0 + m0 + mt * 16 + g;
            if (n < N) {
                float v0 = c[mt][nt][0] + b0, v1 = c[mt][nt][1] + b1;
                v0 = v0 >= 0.f ? v0 : 0.01f * v0; v1 = v1 >= 0.f ? v1 : 0.01f * v1;
                *(half2*)(g_Hh + ((size_t)t * N + n) * D + col) = __floats2half2_rn(v0, v1);
            }
            int n8 = n + 8;
            if (n8 < N) {
                float v0 = c[mt][nt][2] + b0, v1 = c[mt][nt][3] + b1;
                v0 = v0 >= 0.f ? v0 : 0.01f * v0; v1 = v1 >= 0.f ? v1 : 0.01f * v1;
                *(half2*)(g_Hh + ((size_t)t * N + n8) * D + col) = __floats2half2_rn(v0, v1);
            }
        }
    }
}

// ================= fused agg GEMM: gather-in-loader, 20 chunks (K=640) =================
__global__ __launch_bounds__(256, 2) void gemm_agg_fused(const int* __restrict__ node_type,
                                                         const float* __restrict__ b_agg, int N) {
    extern __shared__ __half smh[];
    __shared__ float sBias[128];
    __shared__ float sRed[128];
    __shared__ int sTyp[128];
    __shared__ int sDeg[TMAX][128];
    __shared__ float sInv[TMAX][128];
    uint32_t smBase = smem_u32(smh);

    int n0 = blockIdx.x * 128;
    int tid = threadIdx.x, wid = tid >> 5, lane = tid & 31;
    if (tid < 128) {
        sBias[tid] = b_agg[tid];
        sRed[tid] = 0.f;
        int n = n0 + tid;
        sTyp[tid] = (n < N) ? node_type[n] : 0;
    }
    for (int i = tid; i < TMAX * 128; i += 256) {
        int ch = i >> 7, r = i & 127;
        int n = n0 + r;
        int dg = (n < N) ? g_CUR[ch * N + n] : 0;
        if (dg > BK) dg = BK;
        sDeg[ch][r] = dg;
        sInv[ch][r] = (dg > 0) ? 1.0f / (float)dg : 0.f;
    }
    __syncthreads();

    // A fill: slot chunks compute neighbor means in-loader; self chunk gathers H rows
    auto fillA = [&](int cc, int s) {
        int ch = cc >> 2, kc = cc & 3;
        __half* aBase = smh + (size_t)s * STG_HALFS;
#pragma unroll
        for (int i = 0; i < 2; i++) {
            int idx = tid + i * 256;
            int row = idx >> 2, c = idx & 3;
            int n = n0 + row;
            __half* dst = aBase + row * ASTH + c * 8;
            if (ch < TMAX) {
                int deg = sDeg[ch][row];
                const int* bucket = g_CSR + ((size_t)ch * N + n) * BK;
                float acc0 = 0.f, acc1 = 0.f, acc2 = 0.f, acc3 = 0.f;
                float acc4 = 0.f, acc5 = 0.f, acc6 = 0.f, acc7 = 0.f;
                int sn = (deg > 0) ? __ldg(bucket) : 0;
                for (int e = 0; e < deg; e++) {
                    int sv = sn;
                    if (e + 1 < deg) sn = __ldg(bucket + e + 1);
                    uint4 v = *(const uint4*)(g_Hh + ((size_t)ch * N + sv) * D + kc * 32 + c * 8);
                    float2 f0 = __half22float2(*(half2*)&v.x);
                    float2 f1 = __half22float2(*(half2*)&v.y);
                    float2 f2 = __half22float2(*(half2*)&v.z);
                    float2 f3 = __half22float2(*(half2*)&v.w);
                    acc0 += f0.x; acc1 += f0.y; acc2 += f1.x; acc3 += f1.y;
                    acc4 += f2.x; acc5 += f2.y; acc6 += f3.x; acc7 += f3.y;
                }
                float inv = sInv[ch][row];
                half2 h0 = __floats2half2_rn(acc0 * inv, acc1 * inv);
                half2 h1 = __floats2half2_rn(acc2 * inv, acc3 * inv);
                half2 h2 = __floats2half2_rn(acc4 * inv, acc5 * inv);
                half2 h3 = __floats2half2_rn(acc6 * inv, acc7 * inv);
                uint4 o;
                o.x = *(uint32_t*)&h0; o.y = *(uint32_t*)&h1;
                o.z = *(uint32_t*)&h2; o.w = *(uint32_t*)&h3;
                *(uint4*)dst = o;
            } else {
                uint4 o = make_uint4(0, 0, 0, 0);
                if (n < N)
                    o = *(const uint4*)(g_Hh + ((size_t)sTyp[row] * N + n) * D + kc * 32 + c * 8);
                *(uint4*)dst = o;
            }
        }
    };
    auto loadB = [&](int cc, int s) {
        uint32_t bBase = smBase + ((uint32_t)s * STG_HALFS + A_HALFS) * 2;
#pragma unroll
        for (int i = 0; i < 2; i++) {
            int idx = tid + i * 256;
            int row = idx >> 2, c = idx & 3;
            cpa16(bBase + (uint32_t)(row * BSTH + c * 8) * 2,
                  g_WaggH + (size_t)row * KAGG + cc * 32 + c * 8, 1);
        }
        cpa_commit();
    };

    int m0 = (wid & 3) * 32, nw = (wid >> 2) * 64;
    int g = lane >> 2, tg = lane & 3;

    float c[2][8][4];
#pragma unroll
    for (int mt = 0; mt < 2; mt++)
#pragma unroll
        for (int nt = 0; nt < 8; nt++)
#pragma unroll
            for (int j = 0; j < 4; j++) c[mt][nt][j] = 0.f;

    loadB(0, 0);
    fillA(0, 0);
    for (int cc = 0; cc < 20; cc++) {
        int buf = cc & 1;
        if (cc + 1 < 20) {
            loadB(cc + 1, buf ^ 1);
            fillA(cc + 1, buf ^ 1);
            cpa_wait<1>();
        } else {
            cpa_wait<0>();
        }
        __syncthreads();
        const __half* As = smh + buf * STG_HALFS;
        const __half* Bs = As + A_HALFS;
#pragma unroll
        for (int s16 = 0; s16 < 2; s16++) {
            uint32_t a[2][4], b[8][2];
#pragma unroll
            for (int mt = 0; mt < 2; mt++) {
                const __half* ap = As + (m0 + mt * 16 + g) * ASTH + s16 * 16 + 2 * tg;
                a[mt][0] = ldh2(ap);
                a[mt][1] = ldh2(ap + 8 * ASTH);
                a[mt][2] = ldh2(ap + 8);
                a[mt][3] = ldh2(ap + 8 * ASTH + 8);
            }
#pragma unroll
            for (int nt = 0; nt < 8; nt++) {
                const __half* bp = Bs + (nw + nt * 8 + g) * BSTH + s16 * 16 + 2 * tg;
                b[nt][0] = ldh2(bp);
                b[nt][1] = ldh2(bp + 8);
            }
#pragma unroll
            for (int mt = 0; mt < 2; mt++)
#pragma unroll
                for (int nt = 0; nt < 8; nt++) mma16(c[mt][nt], a[mt], b[nt]);
        }
        __syncthreads();
    }

    // epilogue: sigmoid + node-sum per output column
#pragma unroll
    for (int nt = 0; nt < 8; nt++) {
        int col = nw + nt * 8 + 2 * tg;
        float b0 = sBias[col], b1 = sBias[col + 1];
        float s0 = 0.f, s1 = 0.f;
#pragma unroll
        for (int mt = 0; mt < 2; mt++) {
            int n = n0 + m0 + mt * 16 + g;
            if (n < N) {
                s0 += 1.0f / (1.0f + expf(-(c[mt][nt][0] + b0)));
                s1 += 1.0f / (1.0f + expf(-(c[mt][nt][1] + b1)));
            }
            if (n + 8 < N) {
                s0 += 1.0f / (1.0f + expf(-(c[mt][nt][2] + b0)));
                s1 += 1.0f / (1.0f + expf(-(c[mt][nt][3] + b1)));
            }
        }
#pragma unroll
        for (int o = 4; o < 32; o <<= 1) {
            s0 += __shfl_xor_sync(0xffffffffu, s0, o);
            s1 += __shfl_xor_sync(0xffffffffu, s1, o);
        }
        if (lane < 4) {
            atomicAdd(&sRed[col], s0);
            atomicAdd(&sRed[col + 1], s1);
        }
    }
    __syncthreads();
    if (tid < 128) atomicAdd(&g_SUM[tid], sRed[tid]);
}

__global__ void finalize(float* __restrict__ out, int N) {
    int i = threadIdx.x;
    if (i < D) out[i] = g_SUM[i] * (1.0f / (float)N);
}

// ================= launch =================
extern "C" void kernel_launch(void* const* d_in, const int* in_sizes, int n_in,
                              void* d_out, int out_size) {
    const float* node_feat = (const float*)d_in[0];
    const float* W_content = (const float*)d_in[1];
    const float* b_content = (const float*)d_in[2];
    const float* W_agg     = (const float*)d_in[3];
    const float* b_agg     = (const float*)d_in[4];
    const int*   edge_src  = (const int*)d_in[5];
    const int*   edge_dst  = (const int*)d_in[6];
    const int*   node_type = (const int*)d_in[7];

    int Dd = in_sizes[4];              // 128
    int T  = in_sizes[2] / Dd;         // 4
    int N  = in_sizes[7];              // 100000
    int TE = in_sizes[5];              // 3.2M
    int E  = TE / T;                   // 800000
    (void)n_in; (void)out_size; (void)Dd;

    cudaFuncSetAttribute(gemm_content_mma, cudaFuncAttributeMaxDynamicSharedMemorySize, SMEM_BYTES);
    cudaFuncSetAttribute(gemm_agg_fused,   cudaFuncAttributeMaxDynamicSharedMemorySize, SMEM_BYTES);

    int ntiles = (N + 127) / 128;

    // fork/join resources (created at most a handful of times — correctness + capture calls)
    cudaStream_t sSide;
    cudaEvent_t evFork, evJoin;
    cudaStreamCreateWithFlags(&sSide, cudaStreamNonBlocking);
    cudaEventCreateWithFlags(&evFork, cudaEventDisableTiming);
    cudaEventCreateWithFlags(&evJoin, cudaEventDisableTiming);

    zero_kernel<<<512, 256>>>();

    // fork: scatter runs parallel to converts + content GEMM
    cudaEventRecord(evFork, 0);
    cudaStreamWaitEvent(sSide, evFork, 0);
    scatter_kernel<<<(TE + 255) / 256, 256, 0, sSide>>>(edge_src, edge_dst, E, N, TE);
    cudaEventRecord(evJoin, sSide);

    convert_feat<<<(N * D / 2 + 255) / 256, 256>>>(node_feat, N * D / 2);
    convert_WC<<<(T * D * D / 2 + 255) / 256, 256>>>(W_content, T * D * D / 2);
    transpose_Wagg<<<dim3(KAGG / 32, D / 32), dim3(32, 8)>>>(W_agg);
    gemm_content_mma<<<dim3(ntiles, T), 256, SMEM_BYTES>>>(b_content, N);

    // join: fused agg needs both content H and scatter buckets
    cudaStreamWaitEvent(0, evJoin, 0);
    gemm_agg_fused<<<ntiles, 256, SMEM_BYTES>>>(node_type, b_agg, N);
    finalize<<<1, D>>>((float*)d_out, N);
}

// round 13
// speedup vs baseline: 1.3640x; 1.3640x over previous
#include <cuda_runtime.h>
#include <cuda_fp16.h>
#include <cstdint>
#include <math.h>

#define D 128
#define NMAX 100000
#define TMAX 4
#define KAGG ((TMAX + 1) * D)    // 640
#define BK 48                    // per-(type,node) neighbor bucket capacity
#define ASTH 40                  // A chunk row stride (halfs): conflict-free frag loads
#define BSTH 40                  // B chunk row stride (halfs)
#define A_HALFS (128 * ASTH)     // 5120
#define B_HALFS (128 * BSTH)     // 5120
#define STG_HALFS (A_HALFS + B_HALFS)      // 10240
#define SMEM_BYTES (2 * STG_HALFS * 2)     // 40960

// ---------------- device scratch ----------------
__device__ __half g_featH[(size_t)NMAX * D];            // feat fp16 [n][d]
__device__ __half g_WCH[(size_t)TMAX * D * D];          // W_content fp16 [t][o][d]
__device__ __half g_WaggH[(size_t)D * KAGG];            // W_agg^T fp16 [o][k]
__device__ __half g_Hh[(size_t)TMAX * NMAX * D];        // H fp16 [t][n][o]
__device__ __half g_ACCh[(size_t)TMAX * NMAX * D];      // mean-agg fp16 [t][n][d]
__device__ int    g_CSR[(size_t)TMAX * NMAX * BK];      // neighbor buckets
__device__ int    g_CUR[TMAX * NMAX];                   // bucket cursors / degrees
__device__ float  g_SUM[D];

// ---------------- helpers ----------------
__device__ __forceinline__ uint32_t smem_u32(const void* p) {
    uint32_t a;
    asm("{ .reg .u64 t; cvta.to.shared.u64 t, %1; cvt.u32.u64 %0, t; }" : "=r"(a) : "l"(p));
    return a;
}
__device__ __forceinline__ void cpa16(uint32_t dst, const void* src, int valid) {
    asm volatile("cp.async.ca.shared.global [%0], [%1], 16, %2;"
                 :: "r"(dst), "l"(src), "r"(valid ? 16 : 0));
}
__device__ __forceinline__ void cpa_commit() { asm volatile("cp.async.commit_group;" ::: "memory"); }
template <int NN> __device__ __forceinline__ void cpa_wait() {
    asm volatile("cp.async.wait_group %0;" :: "n"(NN) : "memory");
}
__device__ __forceinline__ void mma16(float* c, const uint32_t* a, const uint32_t* b) {
    asm volatile("mma.sync.aligned.m16n8k16.row.col.f32.f16.f16.f32 "
                 "{%0,%1,%2,%3},{%4,%5,%6,%7},{%8,%9},{%0,%1,%2,%3};"
                 : "+f"(c[0]), "+f"(c[1]), "+f"(c[2]), "+f"(c[3])
                 : "r"(a[0]), "r"(a[1]), "r"(a[2]), "r"(a[3]), "r"(b[0]), "r"(b[1]));
}
__device__ __forceinline__ uint32_t ldh2(const __half* p) { return *(const uint32_t*)p; }

// ---------------- zero cursors + sums ----------------
__global__ void zero_kernel() {
    int i = blockIdx.x * blockDim.x + threadIdx.x;
    int stride = gridDim.x * blockDim.x;
    for (int k = i; k < TMAX * NMAX; k += stride) g_CUR[k] = 0;
    if (i < D) g_SUM[i] = 0.f;
}

// ---------------- fp32 -> fp16 converts ----------------
__global__ void convert_feat(const float* __restrict__ f, int n2) {
    int i = blockIdx.x * blockDim.x + threadIdx.x;
    if (i < n2) {
        float2 v = ((const float2*)f)[i];
        ((half2*)g_featH)[i] = __floats2half2_rn(v.x, v.y);
    }
}
__global__ void convert_WC(const float* __restrict__ W, int n2) {
    int i = blockIdx.x * blockDim.x + threadIdx.x;
    if (i < n2) {
        float2 v = ((const float2*)W)[i];
        ((half2*)g_WCH)[i] = __floats2half2_rn(v.x, v.y);
    }
}
// W_agg [k=640][o=128] -> g_WaggH [o][k] fp16
__global__ void transpose_Wagg(const float* __restrict__ W) {
    __shared__ float t[32][33];
    int k0 = blockIdx.x * 32, o0 = blockIdx.y * 32;
    int tx = threadIdx.x, ty = threadIdx.y;
#pragma unroll
    for (int i = 0; i < 4; i++)
        t[ty + i * 8][tx] = W[(size_t)(k0 + ty + i * 8) * D + o0 + tx];
    __syncthreads();
#pragma unroll
    for (int i = 0; i < 4; i++)
        g_WaggH[(size_t)(o0 + ty + i * 8) * KAGG + k0 + tx] = __float2half(t[tx][ty + i * 8]);
}

// ---------------- scatter edges into buckets (int atomics only) ----------------
__global__ void scatter_kernel(const int* __restrict__ src, const int* __restrict__ dst,
                               int E, int N, int TE) {
    int g = blockIdx.x * blockDim.x + threadIdx.x;
    if (g >= TE) return;
    int t = g / E;
    int d = __ldg(dst + g);
    int s = __ldg(src + g);
    int tn = t * N + d;
    int pos = atomicAdd(&g_CUR[tn], 1);
    if (pos < BK) g_CSR[(size_t)tn * BK + pos] = s;
}

// ---------------- gather: warp per (type,node), mean of neighbor H rows ----------------
__global__ void gather_kernel(int N, int T) {
    int w = (int)((blockIdx.x * blockDim.x + threadIdx.x) >> 5);
    int lane = threadIdx.x & 31;
    if (w >= T * N) return;
    int t = w / N;
    int deg = g_CUR[w];
    if (deg > BK) deg = BK;
    const int* bucket = g_CSR + (size_t)w * BK;
    const uint2* hb = (const uint2*)(g_Hh + (size_t)t * N * D);
    float4 acc = make_float4(0.f, 0.f, 0.f, 0.f);
    int s_next = (deg > 0) ? __ldg(bucket) : 0;
    for (int i = 0; i < deg; i++) {
        int s = s_next;
        if (i + 1 < deg) s_next = __ldg(bucket + i + 1);
        uint2 v = hb[(size_t)s * 32 + lane];       // 4 halfs
        float2 f0 = __half22float2(*(half2*)&v.x);
        float2 f1 = __half22float2(*(half2*)&v.y);
        acc.x += f0.x; acc.y += f0.y; acc.z += f1.x; acc.w += f1.y;
    }
    float inv = (deg > 0) ? 1.0f / (float)deg : 0.f;
    half2 h0 = __floats2half2_rn(acc.x * inv, acc.y * inv);
    half2 h1 = __floats2half2_rn(acc.z * inv, acc.w * inv);
    uint2 o; o.x = *(uint32_t*)&h0; o.y = *(uint32_t*)&h1;
    ((uint2*)(g_ACCh + (size_t)w * D))[lane] = o;
}

// ================= content GEMM: fp16 mma, cp.async double-buffered =================
__global__ __launch_bounds__(256, 2) void gemm_content_mma(const float* __restrict__ bc, int N) {
    extern __shared__ __half smh[];
    __shared__ float sBias[128];
    uint32_t smBase = smem_u32(smh);

    int t = blockIdx.y;
    int n0 = blockIdx.x * 128;
    int tid = threadIdx.x, wid = tid >> 5, lane = tid & 31;
    if (tid < 128) sBias[tid] = bc[t * D + tid];

    const __half* wc = g_WCH + (size_t)t * D * D;

    auto load_chunk = [&](int kc, int s) {
        uint32_t aBase = smBase + (uint32_t)s * STG_HALFS * 2;
        uint32_t bBase = aBase + A_HALFS * 2;
#pragma unroll
        for (int i = 0; i < 2; i++) {
            int idx = tid + i * 256;
            int row = idx >> 2, c = idx & 3;
            int n = n0 + row;
            cpa16(aBase + (uint32_t)(row * ASTH + c * 8) * 2,
                  g_featH + (size_t)n * D + kc * 32 + c * 8, n < N);
            cpa16(bBase + (uint32_t)(row * BSTH + c * 8) * 2,
                  wc + (size_t)row * D + kc * 32 + c * 8, 1);
        }
        cpa_commit();
    };

    int m0 = (wid & 3) * 32, nw = (wid >> 2) * 64;
    int g = lane >> 2, tg = lane & 3;

    float c[2][8][4];
#pragma unroll
    for (int mt = 0; mt < 2; mt++)
#pragma unroll
        for (int nt = 0; nt < 8; nt++)
#pragma unroll
            for (int j = 0; j < 4; j++) c[mt][nt][j] = 0.f;

    load_chunk(0, 0);
    for (int cc = 0; cc < 4; cc++) {
        if (cc + 1 < 4) { load_chunk(cc + 1, (cc + 1) & 1); cpa_wait<1>(); }
        else            { cpa_wait<0>(); }
        __syncthreads();
        const __half* As = smh + (cc & 1) * STG_HALFS;
        const __half* Bs = As + A_HALFS;
#pragma unroll
        for (int s16 = 0; s16 < 2; s16++) {
            uint32_t a[2][4], b[8][2];
#pragma unroll
            for (int mt = 0; mt < 2; mt++) {
                const __half* ap = As + (m0 + mt * 16 + g) * ASTH + s16 * 16 + 2 * tg;
                a[mt][0] = ldh2(ap);
                a[mt][1] = ldh2(ap + 8 * ASTH);
                a[mt][2] = ldh2(ap + 8);
                a[mt][3] = ldh2(ap + 8 * ASTH + 8);
            }
#pragma unroll
            for (int nt = 0; nt < 8; nt++) {
                const __half* bp = Bs + (nw + nt * 8 + g) * BSTH + s16 * 16 + 2 * tg;
                b[nt][0] = ldh2(bp);
                b[nt][1] = ldh2(bp + 8);
            }
#pragma unroll
            for (int mt = 0; mt < 2; mt++)
#pragma unroll
                for (int nt = 0; nt < 8; nt++) mma16(c[mt][nt], a[mt], b[nt]);
        }
        __syncthreads();
    }

#pragma unroll
    for (int mt = 0; mt < 2; mt++) {
#pragma unroll
        for (int nt = 0; nt < 8; nt++) {
            int col = nw + nt * 8 + 2 * tg;
            float b0 = sBias[col], b1 = sBias[col + 1];
            int n = n0 + m0 + mt * 16 + g;
            if (n < N) {
                float v0 = c[mt][nt][0] + b0, v1 = c[mt][nt][1] + b1;
                v0 = v0 >= 0.f ? v0 : 0.01f * v0; v1 = v1 >= 0.f ? v1 : 0.01f * v1;
                *(half2*)(g_Hh + ((size_t)t * N + n) * D + col) = __floats2half2_rn(v0, v1);
            }
            int n8 = n + 8;
            if (n8 < N) {
                float v0 = c[mt][nt][2] + b0, v1 = c[mt][nt][3] + b1;
                v0 = v0 >= 0.f ? v0 : 0.01f * v0; v1 = v1 >= 0.f ? v1 : 0.01f * v1;
                *(half2*)(g_Hh + ((size_t)t * N + n8) * D + col) = __floats2half2_rn(v0, v1);
            }
        }
    }
}

// ================= agg GEMM: fp16 mma, 20 chunks (K=640) + sigmoid + mean =================
__global__ __launch_bounds__(256, 2) void gemm_agg_mma(const int* __restrict__ node_type,
                                                       const float* __restrict__ b_agg, int N) {
    extern __shared__ __half smh[];
    __shared__ float sBias[128];
    __shared__ float sRed[128];
    __shared__ int sTyp[128];
    uint32_t smBase = smem_u32(smh);

    int n0 = blockIdx.x * 128;
    int tid = threadIdx.x, wid = tid >> 5, lane = tid & 31;
    if (tid < 128) {
        sBias[tid] = b_agg[tid];
        sRed[tid] = 0.f;
        int n = n0 + tid;
        sTyp[tid] = (n < N) ? node_type[n] : 0;
    }
    __syncthreads();

    auto load_chunk = [&](int cc, int s) {
        int ch = cc >> 2, kc = cc & 3;
        uint32_t aBase = smBase + (uint32_t)s * STG_HALFS * 2;
        uint32_t bBase = aBase + A_HALFS * 2;
#pragma unroll
        for (int i = 0; i < 2; i++) {
            int idx = tid + i * 256;
            int row = idx >> 2, c = idx & 3;
            int n = n0 + row;
            const __half* src;
            if (ch < 4) src = g_ACCh + ((size_t)ch * N + n) * D + kc * 32 + c * 8;
            else        src = g_Hh + ((size_t)sTyp[row] * N + n) * D + kc * 32 + c * 8;
            cpa16(aBase + (uint32_t)(row * ASTH + c * 8) * 2, src, n < N);
            cpa16(bBase + (uint32_t)(row * BSTH + c * 8) * 2,
                  g_WaggH + (size_t)row * KAGG + cc * 32 + c * 8, 1);
        }
        cpa_commit();
    };

    int m0 = (wid & 3) * 32, nw = (wid >> 2) * 64;
    int g = lane >> 2, tg = lane & 3;

    float c[2][8][4];
#pragma unroll
    for (int mt = 0; mt < 2; mt++)
#pragma unroll
        for (int nt = 0; nt < 8; nt++)
#pragma unroll
            for (int j = 0; j < 4; j++) c[mt][nt][j] = 0.f;

    load_chunk(0, 0);
    for (int cc = 0; cc < 20; cc++) {
        if (cc + 1 < 20) { load_chunk(cc + 1, (cc + 1) & 1); cpa_wait<1>(); }
        else             { cpa_wait<0>(); }
        __syncthreads();
        const __half* As = smh + (cc & 1) * STG_HALFS;
        const __half* Bs = As + A_HALFS;
#pragma unroll
        for (int s16 = 0; s16 < 2; s16++) {
            uint32_t a[2][4], b[8][2];
#pragma unroll
            for (int mt = 0; mt < 2; mt++) {
                const __half* ap = As + (m0 + mt * 16 + g) * ASTH + s16 * 16 + 2 * tg;
                a[mt][0] = ldh2(ap);
                a[mt][1] = ldh2(ap + 8 * ASTH);
                a[mt][2] = ldh2(ap + 8);
                a[mt][3] = ldh2(ap + 8 * ASTH + 8);
            }
#pragma unroll
            for (int nt = 0; nt < 8; nt++) {
                const __half* bp = Bs + (nw + nt * 8 + g) * BSTH + s16 * 16 + 2 * tg;
                b[nt][0] = ldh2(bp);
                b[nt][1] = ldh2(bp + 8);
            }
#pragma unroll
            for (int mt = 0; mt < 2; mt++)
#pragma unroll
                for (int nt = 0; nt < 8; nt++) mma16(c[mt][nt], a[mt], b[nt]);
        }
        __syncthreads();
    }

    // epilogue: sigmoid + node-sum per output column
#pragma unroll
    for (int nt = 0; nt < 8; nt++) {
        int col = nw + nt * 8 + 2 * tg;
        float b0 = sBias[col], b1 = sBias[col + 1];
        float s0 = 0.f, s1 = 0.f;
#pragma unroll
        for (int mt = 0; mt < 2; mt++) {
            int n = n0 + m0 + mt * 16 + g;
            if (n < N) {
                s0 += 1.0f / (1.0f + expf(-(c[mt][nt][0] + b0)));
                s1 += 1.0f / (1.0f + expf(-(c[mt][nt][1] + b1)));
            }
            if (n + 8 < N) {
                s0 += 1.0f / (1.0f + expf(-(c[mt][nt][2] + b0)));
                s1 += 1.0f / (1.0f + expf(-(c[mt][nt][3] + b1)));
            }
        }
#pragma unroll
        for (int o = 4; o < 32; o <<= 1) {
            s0 += __shfl_xor_sync(0xffffffffu, s0, o);
            s1 += __shfl_xor_sync(0xffffffffu, s1, o);
        }
        if (lane < 4) {
            atomicAdd(&sRed[col], s0);
            atomicAdd(&sRed[col + 1], s1);
        }
    }
    __syncthreads();
    if (tid < 128) atomicAdd(&g_SUM[tid], sRed[tid]);
}

__global__ void finalize(float* __restrict__ out, int N) {
    int i = threadIdx.x;
    if (i < D) out[i] = g_SUM[i] * (1.0f / (float)N);
}

// ================= launch =================
extern "C" void kernel_launch(void* const* d_in, const int* in_sizes, int n_in,
                              void* d_out, int out_size) {
    const float* node_feat = (const float*)d_in[0];
    const float* W_content = (const float*)d_in[1];
    const float* b_content = (const float*)d_in[2];
    const float* W_agg     = (const float*)d_in[3];
    const float* b_agg     = (const float*)d_in[4];
    const int*   edge_src  = (const int*)d_in[5];
    const int*   edge_dst  = (const int*)d_in[6];
    const int*   node_type = (const int*)d_in[7];

    int Dd = in_sizes[4];              // 128
    int T  = in_sizes[2] / Dd;         // 4
    int N  = in_sizes[7];              // 100000
    int TE = in_sizes[5];              // 3.2M
    int E  = TE / T;                   // 800000
    (void)n_in; (void)out_size; (void)Dd;

    cudaFuncSetAttribute(gemm_content_mma, cudaFuncAttributeMaxDynamicSharedMemorySize, SMEM_BYTES);
    cudaFuncSetAttribute(gemm_agg_mma,     cudaFuncAttributeMaxDynamicSharedMemorySize, SMEM_BYTES);

    int ntiles = (N + 127) / 128;

    // fork/join resources: created once, reused every call (capture-safe)
    static cudaStream_t sSide = nullptr;
    static cudaEvent_t evFork = nullptr, evJoin = nullptr;
    if (!sSide) {
        cudaStreamCreateWithFlags(&sSide, cudaStreamNonBlocking);
        cudaEventCreateWithFlags(&evFork, cudaEventDisableTiming);
        cudaEventCreateWithFlags(&evJoin, cudaEventDisableTiming);
    }

    zero_kernel<<<512, 256>>>();

    // fork: scatter (buckets) runs parallel to converts + content GEMM
    cudaEventRecord(evFork, 0);
    cudaStreamWaitEvent(sSide, evFork, 0);
    scatter_kernel<<<(TE + 255) / 256, 256, 0, sSide>>>(edge_src, edge_dst, E, N, TE);
    cudaEventRecord(evJoin, sSide);

    convert_feat<<<(N * D / 2 + 255) / 256, 256>>>(node_feat, N * D / 2);
    convert_WC<<<(T * D * D / 2 + 255) / 256, 256>>>(W_content, T * D * D / 2);
    transpose_Wagg<<<dim3(KAGG / 32, D / 32), dim3(32, 8)>>>(W_agg);
    gemm_content_mma<<<dim3(ntiles, T), 256, SMEM_BYTES>>>(b_content, N);

    // join: gather needs both content H and scatter buckets
    cudaStreamWaitEvent(0, evJoin, 0);
    gather_kernel<<<(T * N * 32 + 255) / 256, 256>>>(N, T);
    gemm_agg_mma<<<ntiles, 256, SMEM_BYTES>>>(node_type, b_agg, N);
    finalize<<<1, D>>>((float*)d_out, N);
}